// round 2
// baseline (speedup 1.0000x reference)
#include <cuda_runtime.h>
#include <cstdint>
#include <cstddef>

#define BATCHN 10
#define HID    128
#define OUTD   7
#define TLEN   2048
#define NCTA   8
#define KPC    16      // HID / NCTA hidden units owned per CTA
#define TPB    320     // 64 gate-rows * 5 batch-pairs; 10 warps (warp w <-> batch w for logits)

typedef unsigned long long ull;

__device__ __forceinline__ uint32_t sm2u(const void* p) {
    return (uint32_t)__cvta_generic_to_shared(const_cast<void*>(p));
}
__device__ __forceinline__ uint32_t ctarank() {
    uint32_t r; asm("mov.u32 %0, %%cluster_ctarank;" : "=r"(r)); return r;
}
// weak 4B store into cluster CTA rk's SMEM at same offset as local addr
__device__ __forceinline__ void dst_f32(uint32_t saddr, uint32_t rk, float v) {
    uint32_t ra;
    asm volatile("mapa.shared::cluster.u32 %0, %1, %2;" : "=r"(ra) : "r"(saddr), "r"(rk));
    asm volatile("st.shared::cluster.f32 [%0], %1;" :: "r"(ra), "f"(v) : "memory");
}
// release-arrive on cluster CTA rk's mbarrier (orders this thread's prior cluster stores)
__device__ __forceinline__ void arrive_remote(uint32_t local_mbar, uint32_t rk) {
    uint32_t ra;
    asm volatile("mapa.shared::cluster.u32 %0, %1, %2;" : "=r"(ra) : "r"(local_mbar), "r"(rk));
    asm volatile("mbarrier.arrive.release.cluster.shared::cluster.b64 _, [%0];" :: "r"(ra) : "memory");
}
#define WAIT_PARITY_CLU(addr, par) do {                                              \
    asm volatile("{\n\t.reg .pred P1;\n\t"                                           \
        "WL%=:\n\t"                                                                  \
        "mbarrier.try_wait.parity.acquire.cluster.shared::cta.b64 P1, [%0], %1, 0x989680;\n\t" \
        "@P1 bra WD%=;\n\t bra WL%=;\n\tWD%=:\n\t}"                                  \
        :: "r"(addr), "r"(par) : "memory");                                          \
} while (0)

__device__ __forceinline__ ull fma2(ull a, ull b, ull c) {
    ull d; asm("fma.rn.f32x2 %0, %1, %2, %3;" : "=l"(d) : "l"(a), "l"(b), "l"(c)); return d;
}
__device__ __forceinline__ ull pk2(float lo, float hi) {
    ull r; asm("mov.b64 %0, {%1, %2};" : "=l"(r) : "f"(lo), "f"(hi)); return r;
}
__device__ __forceinline__ float2 unpk2(ull v) {
    float2 f; asm("mov.b64 {%0, %1}, %2;" : "=f"(f.x), "=f"(f.y) : "l"(v)); return f;
}
__device__ __forceinline__ float fsig(float x)  { return __fdividef(1.f, 1.f + __expf(-x)); }
__device__ __forceinline__ float ftanh(float x) { return 2.f * __fdividef(1.f, 1.f + __expf(-2.f * x)) - 1.f; }

__global__ void __cluster_dims__(NCTA, 1, 1) __launch_bounds__(TPB, 1)
lstm_decoder_kernel(const float* __restrict__ h0,
                    const float* __restrict__ c0,
                    const float* __restrict__ tonehot,   // (TLEN+1, 1, OUTD)
                    const void*  __restrict__ tfraw,     // tf_mask (dtype autodetect)
                    const float* __restrict__ W_ih,      // (4*HID, OUTD)
                    const float* __restrict__ W_hh,      // (4*HID, HID)
                    const float* __restrict__ b_ih,
                    const float* __restrict__ b_hh,
                    const float* __restrict__ W_out,     // (OUTD, HID)
                    const float* __restrict__ b_out,
                    float* __restrict__ out)             // [143360 lp | 1280 hT | 1280 cT]
{
    __shared__ __align__(16) float h_s[2][BATCHN][HID];    // double-buffered hidden state
    __shared__ float gates_s[BATCHN * 64];                 // activated gates, CTA's k-slice
    __shared__ float plog_s[2][NCTA][BATCHN * OUTD];       // partial logits from each CTA
    __shared__ float wih_s[4 * HID * OUTD];
    __shared__ int   xidx_s[BATCHN];
    __shared__ int   tgt_s[TLEN];
    __shared__ unsigned char tf_s[TLEN];
    __shared__ float bout_s[OUTD];
    __shared__ int   tfmode_s;
    __shared__ __align__(8) ull mbar_s;

    const int tid  = threadIdx.x;
    const int lane = tid & 31;
    const int wrp  = tid >> 5;        // warp w owns batch w for the logits path
    const uint32_t rank = ctarank();
    const uint32_t mb   = sm2u(&mbar_s);

    // gate-dot role: thread owns gate row g for the 2 batches of pair bp
    const int bp   = tid / 64;        // batch pair 0..4
    const int r    = tid % 64;        // type*16 + klocal
    const int type = r >> 4;          // 0=i 1=f 2=g 3=o
    const int kl   = r & 15;
    const int g    = type * HID + (int)rank * KPC + kl;

    // W_hh row g packed as 64 x f32x2 in registers
    ull wp[HID / 2];
#pragma unroll
    for (int i = 0; i < HID / 4; i++) {
        float4 v = reinterpret_cast<const float4*>(W_hh + (size_t)g * HID)[i];
        wp[2*i]   = pk2(v.x, v.y);
        wp[2*i+1] = pk2(v.z, v.w);
    }
    const float biasg = b_ih[g] + b_hh[g];
    const int   gbase = g * OUTD;

    // pointwise role: first 160 threads own one (batch, hidden-unit)
    const bool is_pw = tid < BATCHN * KPC;
    const int  pb = tid >> 4;
    const int  pk = tid & 15;
    const int  kg = (int)rank * KPC + pk;
    float cval = 0.f;
    float wout[OUTD];
    if (is_pw) {
        cval = c0[pb * HID + kg];
#pragma unroll
        for (int o = 0; o < OUTD; o++) wout[o] = W_out[o * HID + kg];
    }

    // ---- init ----
    if (tid == 0) {
        asm volatile("mbarrier.init.shared.b64 [%0], %1;" :: "r"(mb), "r"(NCTA * BATCHN * KPC) : "memory");
    }
    for (int i = tid; i < BATCHN * HID; i += TPB) ((float*)h_s[0])[i] = h0[i];
    for (int i = tid; i < 4 * HID * OUTD; i += TPB) wih_s[i] = W_ih[i];
    if (tid < OUTD)   bout_s[tid] = b_out[tid];
    if (tid < BATCHN) xidx_s[tid] = OUTD - 1;     // x0 one-hot at column OUT-1

    if (tid == 0) {   // tf_mask dtype autodetect (int32 / float32 / bytes)
        const int* ip = (const int*)tfraw;
        int mode = 0;
        for (int i = 0; i < 512; i++) {
            int v = ip[i];
            if (v == 0x3f800000) { mode = 1; break; }
            if (v != 0 && v != 1) mode = 2;
        }
        tfmode_s = mode;
    }
    __syncthreads();
    {
        const int mode = tfmode_s;
        for (int s = tid; s < TLEN; s += TPB) {
            unsigned char tv;
            if (mode == 0)      tv = ((const int*)tfraw)[s] != 0;
            else if (mode == 1) tv = ((const float*)tfraw)[s] != 0.f;
            else                tv = ((const unsigned char*)tfraw)[s] != 0;
            tf_s[s] = tv;
            const float* row = tonehot + (size_t)(s + 1) * OUTD;   // exactly one-hot
            int idx = 0; float best = row[0];
#pragma unroll
            for (int o = 1; o < OUTD; o++) { if (row[o] > best) { best = row[o]; idx = o; } }
            tgt_s[s] = idx;
        }
    }
    __syncthreads();
    // all CTAs' mbarrier inits + smem init must precede any remote traffic
    asm volatile("barrier.cluster.arrive.aligned;" ::: "memory");
    asm volatile("barrier.cluster.wait.aligned;"   ::: "memory");

    // ================= main sequential loop =================
    for (int t = 0; t < TLEN; t++) {
        const int p = t & 1;

        if (t > 0) WAIT_PARITY_CLU(mb, (t - 1) & 1);

        // preload previous-step partial logits (warp w = batch w, lanes 0..6)
        float pls[NCTA];
        if (t > 0 && lane < OUTD) {
#pragma unroll
            for (int rr = 0; rr < NCTA; rr++) pls[rr] = plog_s[p][rr][wrp * OUTD + lane];
        }

        // ---- recurrent dot: 128 f32x2 FMAs per thread ----
        ull accA0 = 0ull, accA1 = 0ull, accB0 = 0ull, accB1 = 0ull;
        const ulonglong2* hA16 = reinterpret_cast<const ulonglong2*>(h_s[p][bp * 2]);
        const ulonglong2* hB16 = reinterpret_cast<const ulonglong2*>(h_s[p][bp * 2 + 1]);
#pragma unroll
        for (int i = 0; i < HID / 4; i++) {
            ulonglong2 ua = hA16[i];
            ulonglong2 ub = hB16[i];
            accA0 = fma2(ua.x, wp[2*i],   accA0);
            accA1 = fma2(ua.y, wp[2*i+1], accA1);
            accB0 = fma2(ub.x, wp[2*i],   accB0);
            accB1 = fma2(ub.y, wp[2*i+1], accB1);
        }
        float2 fa0 = unpk2(accA0), fa1 = unpk2(accA1);
        float2 fb0 = unpk2(accB0), fb1 = unpk2(accB1);
        const float dotA = (fa0.x + fa0.y) + (fa1.x + fa1.y);
        const float dotB = (fb0.x + fb0.y) + (fb1.x + fb1.y);

        // ---- finish logits(t-1): per-warp sum + shfl argmax -> xidx ----
        float slog = 0.f, vmax = 0.f;
        if (t > 0) {
            slog = (lane < OUTD) ? bout_s[lane] : -1e30f;
            if (lane < OUTD) {
#pragma unroll
                for (int rr = 0; rr < NCTA; rr++) slog += pls[rr];
            }
            float v = slog;
            int   idx = (lane < OUTD) ? lane : OUTD;
#pragma unroll
            for (int d = 4; d >= 1; d >>= 1) {
                float v2 = __shfl_xor_sync(0xffffffffu, v, d, 8);
                int   i2 = __shfl_xor_sync(0xffffffffu, idx, d, 8);
                if (v2 > v || (v2 == v && i2 < idx)) { v = v2; idx = i2; }
            }
            vmax = v;
            if (lane == 0) xidx_s[wrp] = tf_s[t - 1] ? tgt_s[t - 1] : idx;
        }
        __syncthreads();   // xidx published; also fences gates_s write(t) vs read(t-1) via phase edge

        // ---- gates: one-hot column + bias, activate ----
        {
            float vA = dotA + biasg + wih_s[gbase + xidx_s[bp * 2]];
            float vB = dotB + biasg + wih_s[gbase + xidx_s[bp * 2 + 1]];
            if (type == 2) { vA = ftanh(vA); vB = ftanh(vB); }
            else           { vA = fsig(vA);  vB = fsig(vB);  }
            gates_s[(bp * 2    ) * 64 + r] = vA;
            gates_s[(bp * 2 + 1) * 64 + r] = vB;
        }
        __syncthreads();

        // ---- pointwise, broadcast h, partial logits, arrive ----
        if (is_pw) {
            const float ig = gates_s[pb * 64 +      pk];
            const float fg = gates_s[pb * 64 + 16 + pk];
            const float gg = gates_s[pb * 64 + 32 + pk];
            const float og = gates_s[pb * 64 + 48 + pk];
            cval = fg * cval + ig * gg;
            const float h2 = og * ftanh(cval);

            const uint32_t hoff = sm2u(&h_s[p ^ 1][pb][kg]);
#pragma unroll
            for (uint32_t rr = 0; rr < NCTA; rr++) dst_f32(hoff, rr, h2);

            float pl[OUTD];
#pragma unroll
            for (int o = 0; o < OUTD; o++) pl[o] = h2 * wout[o];
#pragma unroll
            for (int d = 8; d >= 1; d >>= 1) {
#pragma unroll
                for (int o = 0; o < OUTD; o++)
                    pl[o] += __shfl_xor_sync(0xffffffffu, pl[o], d, 16);
            }
            if (pk < OUTD) {
                float myv = pl[0];
#pragma unroll
                for (int o = 1; o < OUTD; o++) if (pk == o) myv = pl[o];
                const uint32_t poff = sm2u(&plog_s[p ^ 1][rank][pb * OUTD + pk]);
#pragma unroll
                for (uint32_t rr = 0; rr < NCTA; rr++) dst_f32(poff, rr, myv);
            }
#pragma unroll
            for (uint32_t rr = 0; rr < NCTA; rr++) arrive_remote(mb, rr);
        }

        // ---- off-critical-path: log-softmax(t-1) + output write ----
        if (t > 0) {
            float e = (lane < OUTD) ? __expf(slog - vmax) : 0.f;
#pragma unroll
            for (int d = 4; d >= 1; d >>= 1)
                e += __shfl_xor_sync(0xffffffffu, e, d, 8);
            const float lse = vmax + __logf(e);
            if (rank == 0 && lane < OUTD)
                out[(size_t)wrp * TLEN * OUTD + (size_t)(t - 1) * OUTD + lane] = slog - lse;
        }
    }

    // ================= epilogue =================
    WAIT_PARITY_CLU(mb, (TLEN - 1) & 1);
    {
        const int p = TLEN & 1;   // 0
        float slog = (lane < OUTD) ? bout_s[lane] : -1e30f;
        if (lane < OUTD) {
#pragma unroll
            for (int rr = 0; rr < NCTA; rr++) slog += plog_s[p][rr][wrp * OUTD + lane];
        }
        float v = slog;
#pragma unroll
        for (int d = 4; d >= 1; d >>= 1) {
            float v2 = __shfl_xor_sync(0xffffffffu, v, d, 8);
            if (v2 > v) v = v2;
        }
        float e = (lane < OUTD) ? __expf(slog - v) : 0.f;
#pragma unroll
        for (int d = 4; d >= 1; d >>= 1)
            e += __shfl_xor_sync(0xffffffffu, e, d, 8);
        const float lse = v + __logf(e);
        if (rank == 0 && lane < OUTD)
            out[(size_t)wrp * TLEN * OUTD + (size_t)(TLEN - 1) * OUTD + lane] = slog - lse;

        if (rank == 0) {
            for (int i = tid; i < BATCHN * HID; i += TPB)
                out[(size_t)BATCHN * TLEN * OUTD + i] = ((float*)h_s[p])[i];
        }
        if (is_pw)
            out[(size_t)BATCHN * TLEN * OUTD + BATCHN * HID + pb * HID + kg] = cval;
    }
}

extern "C" void kernel_launch(void* const* d_in, const int* in_sizes, int n_in,
                              void* d_out, int out_size) {
    (void)in_sizes; (void)n_in; (void)out_size;
    const float* h0    = (const float*)d_in[0];
    const float* c0    = (const float*)d_in[1];
    const float* toh   = (const float*)d_in[2];
    const void*  tf    = d_in[3];
    const float* W_ih  = (const float*)d_in[4];
    const float* W_hh  = (const float*)d_in[5];
    const float* b_ih  = (const float*)d_in[6];
    const float* b_hh  = (const float*)d_in[7];
    const float* W_out = (const float*)d_in[8];
    const float* b_out = (const float*)d_in[9];
    float* out = (float*)d_out;

    lstm_decoder_kernel<<<NCTA, TPB>>>(h0, c0, toh, tf, W_ih, W_hh,
                                       b_ih, b_hh, W_out, b_out, out);
}

// round 3
// speedup vs baseline: 1.6991x; 1.6991x over previous
#include <cuda_runtime.h>
#include <cstdint>
#include <cstddef>

#define BATCHN 10
#define HID    128
#define OUTD   7
#define TLEN   2048
#define NCTA   8
#define KPC    16      // HID / NCTA hidden units owned per CTA
#define TPB    320     // 10 warps; warp w <-> batch w

typedef unsigned long long ull;

__device__ __forceinline__ uint32_t sm2u(const void* p) {
    return (uint32_t)__cvta_generic_to_shared(const_cast<void*>(p));
}
__device__ __forceinline__ uint32_t ctarank() {
    uint32_t r; asm("mov.u32 %0, %%cluster_ctarank;" : "=r"(r)); return r;
}
__device__ __forceinline__ void dst_f32(uint32_t saddr, uint32_t rk, float v) {
    uint32_t ra;
    asm volatile("mapa.shared::cluster.u32 %0, %1, %2;" : "=r"(ra) : "r"(saddr), "r"(rk));
    asm volatile("st.shared::cluster.f32 [%0], %1;" :: "r"(ra), "f"(v) : "memory");
}
__device__ __forceinline__ void dst_u64(uint32_t saddr, uint32_t rk, ull v) {
    uint32_t ra;
    asm volatile("mapa.shared::cluster.u32 %0, %1, %2;" : "=r"(ra) : "r"(saddr), "r"(rk));
    asm volatile("st.shared::cluster.b64 [%0], %1;" :: "r"(ra), "l"(v) : "memory");
}
__device__ __forceinline__ ull fma2(ull a, ull b, ull c) {
    ull d; asm("fma.rn.f32x2 %0, %1, %2, %3;" : "=l"(d) : "l"(a), "l"(b), "l"(c)); return d;
}
__device__ __forceinline__ ull pk2(float lo, float hi) {
    ull r; asm("mov.b64 %0, {%1, %2};" : "=l"(r) : "f"(lo), "f"(hi)); return r;
}
__device__ __forceinline__ float2 unpk2(ull v) {
    float2 f; asm("mov.b64 {%0, %1}, %2;" : "=f"(f.x), "=f"(f.y) : "l"(v)); return f;
}
__device__ __forceinline__ float fsig(float x)  { return __fdividef(1.f, 1.f + __expf(-x)); }
__device__ __forceinline__ float ftanh(float x) { return 2.f * __fdividef(1.f, 1.f + __expf(-2.f * x)) - 1.f; }

#define FULLM 0xffffffffu

__global__ void __cluster_dims__(NCTA, 1, 1) __launch_bounds__(TPB, 1)
lstm_decoder_kernel(const float* __restrict__ h0,
                    const float* __restrict__ c0,
                    const float* __restrict__ tonehot,   // (TLEN+1, 1, OUTD)
                    const void*  __restrict__ tfraw,     // tf_mask (dtype autodetect)
                    const float* __restrict__ W_ih,      // (4*HID, OUTD)
                    const float* __restrict__ W_hh,      // (4*HID, HID)
                    const float* __restrict__ b_ih,
                    const float* __restrict__ b_hh,
                    const float* __restrict__ W_out,     // (OUTD, HID)
                    const float* __restrict__ b_out,
                    float* __restrict__ out)             // [143360 lp | 1280 hT | 1280 cT]
{
    __shared__ __align__(16) float h_s[2][BATCHN][HID];    // double-buffered hidden state
    __shared__ float gates_s[BATCHN * 64];                 // activated gates for CTA's k-slice
    __shared__ float plog_s[2][NCTA][BATCHN * OUTD];       // partial logits per CTA
    __shared__ float wih_s[4 * HID * OUTD];
    __shared__ int   tgt_s[TLEN];
    __shared__ unsigned char tf_s[TLEN];
    __shared__ float bout_s[OUTD];
    __shared__ int   tfmode_s;

    const int tid  = threadIdx.x;
    const int lane = tid & 31;
    const int w    = tid >> 5;           // warp 0..9 == batch 0..9
    const int bp   = w >> 1;             // pair 0..4
    const int whalf= w & 1;
    const int bA   = bp * 2;
    const int bB   = bA + 1;
    const uint32_t rank = ctarank();

    // ---- gate-dot role: thread owns gate row (type, kl) for batches bA, bB ----
    const int r    = whalf * 32 + lane;  // 0..63
    const int type = r >> 4;             // 0=i 1=f 2=g 3=o
    const int kl   = r & 15;
    const int g    = type * HID + (int)rank * KPC + kl;

    ull wp[HID / 2];                     // W_hh row g packed f32x2
#pragma unroll
    for (int i = 0; i < HID / 4; i++) {
        float4 v = reinterpret_cast<const float4*>(W_hh + (size_t)g * HID)[i];
        wp[2*i]   = pk2(v.x, v.y);
        wp[2*i+1] = pk2(v.z, v.w);
    }
    const float biasg = b_ih[g] + b_hh[g];
    const int   gbase = g * OUTD;

    // ---- pointwise role: lanes 0..15 of warp w own (batch w, k=lane) ----
    const int  kg = (int)rank * KPC + lane;          // valid for lane<16
    float cval = 0.f;
    float wout[OUTD];
    if (lane < KPC) {
        cval = c0[w * HID + kg];
#pragma unroll
        for (int o = 0; o < OUTD; o++) wout[o] = W_out[o * HID + kg];
    }

    // ---- init ----
    for (int i = tid; i < BATCHN * HID; i += TPB) ((float*)h_s[0])[i] = h0[i];
    for (int i = tid; i < 4 * HID * OUTD; i += TPB) wih_s[i] = W_ih[i];
    if (tid < OUTD) bout_s[tid] = b_out[tid];
    if (tid == 0) {                                   // tf dtype autodetect
        const int* ip = (const int*)tfraw;
        int mode = 0;
        for (int i = 0; i < 512; i++) {
            int v = ip[i];
            if (v == 0x3f800000) { mode = 1; break; }
            if (v != 0 && v != 1) mode = 2;
        }
        tfmode_s = mode;
    }
    __syncthreads();
    {
        const int mode = tfmode_s;
        for (int s = tid; s < TLEN; s += TPB) {
            unsigned char tv;
            if (mode == 0)      tv = ((const int*)tfraw)[s] != 0;
            else if (mode == 1) tv = ((const float*)tfraw)[s] != 0.f;
            else                tv = ((const unsigned char*)tfraw)[s] != 0;
            tf_s[s] = tv;
            const float* row = tonehot + (size_t)(s + 1) * OUTD;   // exactly one-hot
            int idx = 0; float best = row[0];
#pragma unroll
            for (int o = 1; o < OUTD; o++) { if (row[o] > best) { best = row[o]; idx = o; } }
            tgt_s[s] = idx;
        }
    }
    __syncthreads();
    asm volatile("barrier.cluster.arrive.aligned;" ::: "memory");
    asm volatile("barrier.cluster.wait.aligned;"   ::: "memory");

    // ================= main sequential loop =================
    for (int t = 0; t < TLEN; t++) {
        const int p = t & 1;

        // ---- argmax of logits(t-1) for both of this warp's batches (no smem, no barrier) ----
        int xA = OUTD - 1, xB = OUTD - 1;
        float slog = -1e30f, vmax = -1e30f;
        if (t > 0) {
            const int half = (lane >> 3) & 1;         // 0 -> bA, 1 -> bB (lanes>=16 duplicate)
            const int o    = lane & 7;
            const int b    = bA + half;
            float s = -1e30f;
            if (lane < 16 && o < OUTD) {
                s = bout_s[o];
#pragma unroll
                for (int rr = 0; rr < NCTA; rr++) s += plog_s[p][rr][b * OUTD + o];
            }
            float v = s;
            int   idx = (o < OUTD) ? o : OUTD;
#pragma unroll
            for (int d = 4; d >= 1; d >>= 1) {
                float v2 = __shfl_xor_sync(FULLM, v, d, 8);
                int   i2 = __shfl_xor_sync(FULLM, idx, d, 8);
                if (v2 > v || (v2 == v && i2 < idx)) { v = v2; idx = i2; }
            }
            slog = s; vmax = v;
            const int ia = __shfl_sync(FULLM, idx, 0);
            const int ib = __shfl_sync(FULLM, idx, 8);
            const unsigned char tfv = tf_s[t - 1];
            const int tg = tgt_s[t - 1];
            xA = tfv ? tg : ia;
            xB = tfv ? tg : ib;
        }

        // ---- recurrent dot: 128 f32x2 FMAs ----
        ull accA0 = 0ull, accA1 = 0ull, accB0 = 0ull, accB1 = 0ull;
        const ulonglong2* hA16 = reinterpret_cast<const ulonglong2*>(h_s[p][bA]);
        const ulonglong2* hB16 = reinterpret_cast<const ulonglong2*>(h_s[p][bB]);
#pragma unroll
        for (int i = 0; i < HID / 4; i++) {
            ulonglong2 ua = hA16[i];
            ulonglong2 ub = hB16[i];
            accA0 = fma2(ua.x, wp[2*i],   accA0);
            accA1 = fma2(ua.y, wp[2*i+1], accA1);
            accB0 = fma2(ub.x, wp[2*i],   accB0);
            accB1 = fma2(ub.y, wp[2*i+1], accB1);
        }
        float2 fa0 = unpk2(accA0), fa1 = unpk2(accA1);
        float2 fb0 = unpk2(accB0), fb1 = unpk2(accB1);
        float vA = (fa0.x + fa0.y) + (fa1.x + fa1.y) + biasg + wih_s[gbase + xA];
        float vB = (fb0.x + fb0.y) + (fb1.x + fb1.y) + biasg + wih_s[gbase + xB];
        if (type == 2) { vA = ftanh(vA); vB = ftanh(vB); }
        else           { vA = fsig(vA);  vB = fsig(vB);  }
        gates_s[bA * 64 + r] = vA;
        gates_s[bB * 64 + r] = vB;

        // ---- pair-local exchange (64 threads) ----
        asm volatile("bar.sync %0, 64;" :: "r"(1 + bp) : "memory");

        // ---- pointwise for batch w on lanes 0..15 ----
        if (lane < KPC) {
            const int gb = w * 64 + lane;
            const float ig = gates_s[gb];
            const float fg = gates_s[gb + 16];
            const float gg = gates_s[gb + 32];
            const float og = gates_s[gb + 48];
            cval = fg * cval + ig * gg;
            const float h2 = og * ftanh(cval);

            // packed 8B broadcast of h2 (even lanes carry pair)
            const float h2hi = __shfl_xor_sync(0x0000ffffu, h2, 1, 16);
            if ((lane & 1) == 0) {
                const ull hv = pk2(h2, h2hi);
                const uint32_t hoff = sm2u(&h_s[p ^ 1][w][kg]);
#pragma unroll
                for (uint32_t rr = 0; rr < NCTA; rr++) dst_u64(hoff, rr, hv);
            }

            // partial logits for this CTA's slice, reduced over 16 lanes
            float pl[OUTD];
#pragma unroll
            for (int o = 0; o < OUTD; o++) pl[o] = h2 * wout[o];
#pragma unroll
            for (int d = 8; d >= 1; d >>= 1) {
#pragma unroll
                for (int o = 0; o < OUTD; o++)
                    pl[o] += __shfl_xor_sync(0x0000ffffu, pl[o], d, 16);
            }
            if (lane < OUTD) {
                float myv = pl[0];
#pragma unroll
                for (int o = 1; o < OUTD; o++) if (lane == o) myv = pl[o];
                const uint32_t poff = sm2u(&plog_s[p ^ 1][rank][w * OUTD + lane]);
#pragma unroll
                for (uint32_t rr = 0; rr < NCTA; rr++) dst_f32(poff, rr, myv);
            }
        }

        // ---- cluster sync, with log-softmax(t-1) hidden inside the window ----
        asm volatile("barrier.cluster.arrive.aligned;" ::: "memory");
        if (t > 0 && rank == 0) {
            const int half = (lane >> 3) & 1;
            const int o    = lane & 7;
            float e = (lane < 16 && o < OUTD) ? __expf(slog - vmax) : 0.f;
#pragma unroll
            for (int d = 4; d >= 1; d >>= 1)
                e += __shfl_xor_sync(FULLM, e, d, 8);
            const float lse = vmax + __logf(e);
            if (lane < 16 && o < OUTD && half == whalf)
                out[(size_t)w * TLEN * OUTD + (size_t)(t - 1) * OUTD + o] = slog - lse;
        }
        asm volatile("barrier.cluster.wait.aligned;" ::: "memory");
    }

    // ================= epilogue: logits for t = TLEN-1, final states =================
    {
        const int o = lane & 7;
        float s = -1e30f;
        if (lane < 8 && o < OUTD) {
            s = bout_s[o];
#pragma unroll
            for (int rr = 0; rr < NCTA; rr++) s += plog_s[0][rr][w * OUTD + o];
        }
        float v = s;
#pragma unroll
        for (int d = 4; d >= 1; d >>= 1) {
            float v2 = __shfl_xor_sync(FULLM, v, d, 8);
            if (v2 > v) v = v2;
        }
        float e = (lane < 8 && o < OUTD) ? __expf(s - v) : 0.f;
#pragma unroll
        for (int d = 4; d >= 1; d >>= 1)
            e += __shfl_xor_sync(FULLM, e, d, 8);
        const float lse = v + __logf(e);
        if (rank == 0 && lane < OUTD)
            out[(size_t)w * TLEN * OUTD + (size_t)(TLEN - 1) * OUTD + lane] = s - lse;

        if (rank == 0) {
            for (int i = tid; i < BATCHN * HID; i += TPB)
                out[(size_t)BATCHN * TLEN * OUTD + i] = ((float*)h_s[0])[i];
        }
        if (lane < KPC)
            out[(size_t)BATCHN * TLEN * OUTD + BATCHN * HID + w * HID + kg] = cval;
    }
}

extern "C" void kernel_launch(void* const* d_in, const int* in_sizes, int n_in,
                              void* d_out, int out_size) {
    (void)in_sizes; (void)n_in; (void)out_size;
    const float* h0    = (const float*)d_in[0];
    const float* c0    = (const float*)d_in[1];
    const float* toh   = (const float*)d_in[2];
    const void*  tf    = d_in[3];
    const float* W_ih  = (const float*)d_in[4];
    const float* W_hh  = (const float*)d_in[5];
    const float* b_ih  = (const float*)d_in[6];
    const float* b_hh  = (const float*)d_in[7];
    const float* W_out = (const float*)d_in[8];
    const float* b_out = (const float*)d_in[9];
    float* out = (float*)d_out;

    lstm_decoder_kernel<<<NCTA, TPB>>>(h0, c0, toh, tf, W_ih, W_hh,
                                       b_ih, b_hh, W_out, b_out, out);
}